// round 12
// baseline (speedup 1.0000x reference)
#include <cuda_runtime.h>

// Problem dims
#define B_  2048
#define M_  128
#define D_  512
#define H_  512
#define KU_ 1024

// GEMM tiling: 128x64 tile, BK=16, 256 threads, 8Mx4N micro-tile, M-packed f32x2
#define BM 128
#define BN 64
#define BK 16
#define AS_LD (BM + 4)   // 132
#define WS_LD (BN + 4)   // 68

typedef unsigned long long u64;
typedef unsigned int u32;

// Scratch + flags (device globals — no allocation allowed)
__device__ float g_mi[B_ * H_];
__device__ float g_mt[B_ * H_];
__device__ float g_u [B_ * H_];
__device__ u32   g_ucnt;
__device__ u32   g_mcnt[16];
__device__ u32   g_job;

// ---------------------------------------------------------------------------
__device__ __forceinline__ u32 ld_acq(const u32* p) {
    u32 v; asm volatile("ld.acquire.gpu.global.u32 %0, [%1];" : "=r"(v) : "l"(p)); return v;
}
__device__ __forceinline__ void red_rel(u32* p) {
    asm volatile("red.release.gpu.global.add.u32 [%0], 1;" :: "l"(p) : "memory");
}
__device__ __forceinline__ void fma2(u64& d, u64 a, u64 b) {
    asm volatile("fma.rn.f32x2 %0, %1, %2, %0;" : "+l"(d) : "l"(a), "l"(b));
}
__device__ __forceinline__ u64 pack2(float x) {
    u64 r; asm("mov.b64 %0, {%1, %1};" : "=l"(r) : "f"(x)); return r;
}
__device__ __forceinline__ float2 unpk(u64 v) {
    float2 r; asm("mov.b64 {%0,%1}, %2;" : "=f"(r.x), "=f"(r.y) : "l"(v)); return r;
}

// ---------------------------------------------------------------------------
__device__ __forceinline__ void sts_a(float (*As)[AS_LD], const float4& v, int row, int cv) {
    As[cv + 0][row] = v.x; As[cv + 1][row] = v.y;
    As[cv + 2][row] = v.z; As[cv + 3][row] = v.w;
}
__device__ __forceinline__ void sts_w(float (*Ws)[WS_LD], const float4& v, int row, int cv) {
    Ws[cv + 0][row] = v.x; Ws[cv + 1][row] = v.y;
    Ws[cv + 2][row] = v.z; Ws[cv + 3][row] = v.w;
}

// Inner: 8M (4 packed pairs) x 4N per thread. ty=m-group(0..15), tx=n-group(0..15)
__device__ __forceinline__ void tile_fma(
    u64 acc[4][4], const float (*As)[AS_LD], const float (*Ws)[WS_LD], int ty, int tx)
{
#pragma unroll
    for (int kk = 0; kk < BK; kk++) {
        const u64* ap = reinterpret_cast<const u64*>(&As[kk][ty * 8]);
        ulonglong2 a01 = *reinterpret_cast<const ulonglong2*>(ap);
        ulonglong2 a23 = *reinterpret_cast<const ulonglong2*>(ap + 2);
        float4 w = *reinterpret_cast<const float4*>(&Ws[kk][tx * 4]);
        u64 a0 = a01.x, a1 = a01.y, a2 = a23.x, a3 = a23.y;
        u64 w0 = pack2(w.x), w1 = pack2(w.y), w2 = pack2(w.z), w3 = pack2(w.w);
        fma2(acc[0][0], a0, w0); fma2(acc[1][0], a1, w0);
        fma2(acc[2][0], a2, w0); fma2(acc[3][0], a3, w0);
        fma2(acc[0][1], a0, w1); fma2(acc[1][1], a1, w1);
        fma2(acc[2][1], a2, w1); fma2(acc[3][1], a3, w1);
        fma2(acc[0][2], a0, w2); fma2(acc[1][2], a1, w2);
        fma2(acc[2][2], a2, w2); fma2(acc[3][2], a3, w2);
        fma2(acc[0][3], a0, w3); fma2(acc[1][3], a1, w3);
        fma2(acc[2][3], a2, w3); fma2(acc[3][3], a3, w3);
    }
}

// Generic pipelined phase over K=H_
__device__ __forceinline__ void run_phase(
    u64 acc[4][4],
    const float* __restrict__ A,
    const float* __restrict__ W0, const float* __restrict__ W1,
    float As[2][BK][AS_LD], float Ws[2][BK][WS_LD],
    int bm, int bn, int tid, int ty, int tx)
{
    const int r0  = tid >> 2;
    const int cv  = (tid & 3) << 2;
    const int NT  = H_ / BK;   // 32

    float4 a0, a1, wv;
    {
        a0 = *reinterpret_cast<const float4*>(A + (size_t)(bm + r0) * H_ + cv);
        a1 = *reinterpret_cast<const float4*>(A + (size_t)(bm + r0 + 64) * H_ + cv);
        wv = *reinterpret_cast<const float4*>(W0 + (size_t)(bn + (r0 & 63)) * H_ + cv);
        if (W1) {
            float4 w2 = *reinterpret_cast<const float4*>(W1 + (size_t)(bn + (r0 & 63)) * H_ + cv);
            wv.x += w2.x; wv.y += w2.y; wv.z += w2.z; wv.w += w2.w;
        }
        sts_a(As[0], a0, r0, cv); sts_a(As[0], a1, r0 + 64, cv);
        sts_w(Ws[0], wv, r0 & 63, cv);
    }
    __syncthreads();

    int p = 0;
    for (int t = 0; t < NT; t++) {
        if (t + 1 < NT) {
            int kt = (t + 1) * BK;
            a0 = *reinterpret_cast<const float4*>(A + (size_t)(bm + r0) * H_ + kt + cv);
            a1 = *reinterpret_cast<const float4*>(A + (size_t)(bm + r0 + 64) * H_ + kt + cv);
            wv = *reinterpret_cast<const float4*>(W0 + (size_t)(bn + (r0 & 63)) * H_ + kt + cv);
            if (W1) {
                float4 w2 = *reinterpret_cast<const float4*>(W1 + (size_t)(bn + (r0 & 63)) * H_ + kt + cv);
                wv.x += w2.x; wv.y += w2.y; wv.z += w2.z; wv.w += w2.w;
            }
        }
        tile_fma(acc, As[p], Ws[p], ty, tx);
        if (t + 1 < NT) {
            sts_a(As[p ^ 1], a0, r0, cv); sts_a(As[p ^ 1], a1, r0 + 64, cv);
            sts_w(Ws[p ^ 1], wv, r0 & 63, cv);
        }
        __syncthreads();
        p ^= 1;
    }
}

// ---------------------------------------------------------------------------
__global__ void zero_flags() {
    if (threadIdx.x == 0) { g_ucnt = 0; g_job = 0; }
    if (threadIdx.x < 16) g_mcnt[threadIdx.x] = 0;
}

// ---------------------------------------------------------------------------
// Main fused kernel. grid=384, 256 threads, 2 CTAs/SM forced.
//   CTAs 0..127   : compute (gemm_user -> phase3 -> per-tile wait -> phases 1,2)
//   CTAs 128..383 : mean workers, work-stealing over 4096 tile-ordered
//                   row-mean jobs (job = one (modality,row); tile = 256 jobs).
//   Late-launching workers find the queue empty and exit -> no deadlock.
// ---------------------------------------------------------------------------
__global__ void __launch_bounds__(256, 2) fused_all(
    const float* __restrict__ it,  const float* __restrict__ ii,
    const float* __restrict__ btf, const float* __restrict__ bif,
    const float* __restrict__ Wu,  const float* __restrict__ bu,
    const float* __restrict__ Wli, const float* __restrict__ bli,
    const float* __restrict__ Wri, const float* __restrict__ Wlt,
    const float* __restrict__ blt, const float* __restrict__ Wrt,
    float* __restrict__ out)
{
    __shared__ float As[2][BK][AS_LD];
    __shared__ float Ws[2][BK][WS_LD];
    __shared__ float4 redbuf[128];
    __shared__ int s_job;

    const int cid = blockIdx.x;
    const int tid = threadIdx.x;

    if (cid >= 128) {
        // ================= mean workers (work-stealing) =================
        const int col  = tid & 127;     // float4 column of H/4=128
        const int half = tid >> 7;      // node-range half (0: m<64, 1: m>=64)
        const float s = 1.0f / (float)M_;

        for (;;) {
            if (tid == 0) s_job = (int)atomicAdd(&g_job, 1u);
            __syncthreads();
            int j = s_job;
            __syncthreads();
            if (j >= 4096) break;

            int tile  = j >> 8;
            int inner = j & 255;
            int modal = inner >> 7;
            int row   = tile * 128 + (inner & 127);
            const float* src = modal ? btf : bif;
            float*       dst = modal ? g_mt : g_mi;

            const float4* q = reinterpret_cast<const float4*>(src)
                              + (size_t)row * (M_ * H_ / 4)
                              + (size_t)half * 64 * (H_ / 4) + col;
            float4 s0 = make_float4(0.f, 0.f, 0.f, 0.f);
            float4 s1 = make_float4(0.f, 0.f, 0.f, 0.f);
#pragma unroll
            for (int mb = 0; mb < 64; mb += 16) {
                float4 v[16];
#pragma unroll
                for (int k = 0; k < 16; k++)
                    v[k] = q[(size_t)(mb + k) * (H_ / 4)];
#pragma unroll
                for (int k = 0; k < 16; k += 2) {
                    s0.x += v[k].x;     s0.y += v[k].y;
                    s0.z += v[k].z;     s0.w += v[k].w;
                    s1.x += v[k + 1].x; s1.y += v[k + 1].y;
                    s1.z += v[k + 1].z; s1.w += v[k + 1].w;
                }
            }
            float4 sm = make_float4(s0.x + s1.x, s0.y + s1.y,
                                    s0.z + s1.z, s0.w + s1.w);
            if (half) redbuf[col] = sm;
            __syncthreads();
            if (!half) {
                float4 o = redbuf[col];
                reinterpret_cast<float4*>(dst)[(size_t)row * (H_ / 4) + col] =
                    make_float4((sm.x + o.x) * s, (sm.y + o.y) * s,
                                (sm.z + o.z) * s, (sm.w + o.w) * s);
            }
            __syncthreads();
            if (tid == 0) red_rel(&g_mcnt[tile]);
        }
        return;
    }

    // ================= compute CTAs =================
    const int bm = (cid >> 3) * BM;   // 16 m-tiles
    const int bn = (cid & 7) * BN;    // 8 n-tiles
    const int tx = tid & 15;
    const int ty = tid >> 4;
    const int r0 = tid >> 2;
    const int cv = (tid & 3) << 2;

    // ---- Stage 1: gemm_user tile ----
    {
        u64 acc[4][4];
#pragma unroll
        for (int i = 0; i < 4; i++)
#pragma unroll
            for (int j = 0; j < 4; j++) acc[i][j] = 0ull;

        const int NT = KU_ / BK;   // 64
        float4 a0, a1, wv;
        {
            int kg = cv;
            const float* p0 = (kg < D_) ? (it + (size_t)(bm + r0) * D_ + kg)
                                        : (ii + (size_t)(bm + r0) * D_ + (kg - D_));
            const float* p1 = (kg < D_) ? (it + (size_t)(bm + r0 + 64) * D_ + kg)
                                        : (ii + (size_t)(bm + r0 + 64) * D_ + (kg - D_));
            a0 = *reinterpret_cast<const float4*>(p0);
            a1 = *reinterpret_cast<const float4*>(p1);
            wv = *reinterpret_cast<const float4*>(Wu + (size_t)(bn + (r0 & 63)) * KU_ + cv);
            sts_a(As[0], a0, r0, cv); sts_a(As[0], a1, r0 + 64, cv);
            sts_w(Ws[0], wv, r0 & 63, cv);
        }
        __syncthreads();

        int p = 0;
        for (int t = 0; t < NT; t++) {
            if (t + 1 < NT) {
                int kt = (t + 1) * BK;
                int kg = kt + cv;
                const float* p0 = (kg < D_) ? (it + (size_t)(bm + r0) * D_ + kg)
                                            : (ii + (size_t)(bm + r0) * D_ + (kg - D_));
                const float* p1 = (kg < D_) ? (it + (size_t)(bm + r0 + 64) * D_ + kg)
                                            : (ii + (size_t)(bm + r0 + 64) * D_ + (kg - D_));
                a0 = *reinterpret_cast<const float4*>(p0);
                a1 = *reinterpret_cast<const float4*>(p1);
                wv = *reinterpret_cast<const float4*>(Wu + (size_t)(bn + (r0 & 63)) * KU_ + kt + cv);
            }
            tile_fma(acc, As[p], Ws[p], ty, tx);
            if (t + 1 < NT) {
                sts_a(As[p ^ 1], a0, r0, cv); sts_a(As[p ^ 1], a1, r0 + 64, cv);
                sts_w(Ws[p ^ 1], wv, r0 & 63, cv);
            }
            __syncthreads();
            p ^= 1;
        }

        float4 bb = *reinterpret_cast<const float4*>(bu + bn + tx * 4);
#pragma unroll
        for (int i = 0; i < 4; i++) {
            float2 c0 = unpk(acc[i][0]);
            float2 c1 = unpk(acc[i][1]);
            float2 c2 = unpk(acc[i][2]);
            float2 c3 = unpk(acc[i][3]);
            int r = bm + ty * 8 + 2 * i;
            *reinterpret_cast<float4*>(g_u + (size_t)r * H_ + bn + tx * 4) =
                make_float4(c0.x + bb.x, c1.x + bb.y, c2.x + bb.z, c3.x + bb.w);
            *reinterpret_cast<float4*>(g_u + (size_t)(r + 1) * H_ + bn + tx * 4) =
                make_float4(c0.y + bb.x, c1.y + bb.y, c2.y + bb.z, c3.y + bb.w);
        }
    }
    __syncthreads();
    if (tid == 0) red_rel(&g_ucnt);

    if (tid == 0) { while (ld_acq(&g_ucnt) < 128u) __nanosleep(128); }
    __syncthreads();

    // ---- Stage 2: out accumulation ----
    u64 acc[4][4];
#pragma unroll
    for (int i = 0; i < 4; i++)
#pragma unroll
        for (int j = 0; j < 4; j++) acc[i][j] = 0ull;

    // phase 3 (g_u @ (Wri+Wrt)^T), W-sum folded at load
    run_phase(acc, g_u, Wri, Wrt, As, Ws, bm, bn, tid, ty, tx);

    // wait for this m-tile's means (256 row-mean jobs)
    if (tid == 0) { while (ld_acq(&g_mcnt[bm >> 7]) < 256u) __nanosleep(128); }
    __syncthreads();

    run_phase(acc, g_mi, Wli, (const float*)0, As, Ws, bm, bn, tid, ty, tx);
    run_phase(acc, g_mt, Wlt, (const float*)0, As, Ws, bm, bn, tid, ty, tx);

    // epilogue: + (bli+blt), ReLU
    float4 b1 = *reinterpret_cast<const float4*>(bli + bn + tx * 4);
    float4 b2 = *reinterpret_cast<const float4*>(blt + bn + tx * 4);
    float4 bb = make_float4(b1.x + b2.x, b1.y + b2.y, b1.z + b2.z, b1.w + b2.w);
#pragma unroll
    for (int i = 0; i < 4; i++) {
        float2 c0 = unpk(acc[i][0]);
        float2 c1 = unpk(acc[i][1]);
        float2 c2 = unpk(acc[i][2]);
        float2 c3 = unpk(acc[i][3]);
        int r = bm + ty * 8 + 2 * i;
        *reinterpret_cast<float4*>(out + (size_t)r * H_ + bn + tx * 4) =
            make_float4(fmaxf(c0.x + bb.x, 0.f), fmaxf(c1.x + bb.y, 0.f),
                        fmaxf(c2.x + bb.z, 0.f), fmaxf(c3.x + bb.w, 0.f));
        *reinterpret_cast<float4*>(out + (size_t)(r + 1) * H_ + bn + tx * 4) =
            make_float4(fmaxf(c0.y + bb.x, 0.f), fmaxf(c1.y + bb.y, 0.f),
                        fmaxf(c2.y + bb.z, 0.f), fmaxf(c3.y + bb.w, 0.f));
    }
}

// ---------------------------------------------------------------------------
extern "C" void kernel_launch(void* const* d_in, const int* in_sizes, int n_in,
                              void* d_out, int out_size) {
    (void)in_sizes; (void)n_in; (void)out_size;
    const float* it  = (const float*)d_in[0];
    const float* ii  = (const float*)d_in[1];
    const float* btf = (const float*)d_in[2];
    const float* bif = (const float*)d_in[3];
    const float* Wu  = (const float*)d_in[4];
    const float* bu  = (const float*)d_in[5];
    const float* Wli = (const float*)d_in[6];
    const float* bli = (const float*)d_in[7];
    const float* Wri = (const float*)d_in[8];
    const float* Wlt = (const float*)d_in[9];
    const float* blt = (const float*)d_in[10];
    const float* Wrt = (const float*)d_in[11];
    float* out = (float*)d_out;

    zero_flags<<<1, 32>>>();
    fused_all<<<384, 256>>>(it, ii, btf, bif, Wu, bu, Wli, bli, Wri,
                            Wlt, blt, Wrt, out);
}